// round 12
// baseline (speedup 1.0000x reference)
#include <cuda_runtime.h>

// DelayBuffer, persistent scatter formulation.
//
// Spec: out[b, t, i*D + c] = emb[b, t - d_i, c] if t >= d_i else emb[b, t, c]
//       d_i = (1, 2, 4, 8, 16, 32) = 1 << i
//
// Inverted: input row (b, s) sources out[b, s+d_i, seg i] (when s+d_i < S)
// and out[b, s, seg i] (when s < d_i). One float4 load per thread-task,
// 6-7 coalesced 4 KiB streaming segment stores.
//
// Persistent single-wave launch (1184 CTAs = 148 SM x 8): grid-stride loop
// over all 16384 (b, s) row-tasks with next-iteration load prefetched before
// the current stores, so the store stream never drains at CTA boundaries.

static constexpr int B    = 4;
static constexpr int S    = 4096;
static constexpr int D    = 1024;
static constexpr int D4   = D / 4;      // 256 float4 per segment
static constexpr int ND   = 6;          // number of delays
static constexpr int ROW4 = ND * D4;    // output row width in float4 (1536)
static constexpr int NTASK = B * S;     // 16384 row-tasks
static constexpr int NCTA  = 148 * 8;   // one full wave

__device__ __forceinline__ void scatter_row(float4* __restrict__ out,
                                            int b, int s, int c4, float4 v) {
    float4* const obat = out + (size_t)b * S * ROW4;
#pragma unroll
    for (int i = 0; i < ND; i++) {
        const int d = 1 << i;                 // DELAYS = (1,2,4,8,16,32)
        if (s + d < S)
            __stcs(&obat[(size_t)(s + d) * ROW4 + i * D4 + c4], v);
        if (s < d)
            __stcs(&obat[(size_t)s * ROW4 + i * D4 + c4], v);
    }
}

__global__ __launch_bounds__(D4)
void delay_buffer_persist_kernel(const float4* __restrict__ in,
                                 float4* __restrict__ out) {
    const int c4 = threadIdx.x;          // 0..255 within a segment

    int idx = blockIdx.x;
    if (idx >= NTASK) return;

    // prime the pipeline: load task idx
    float4 v = __ldg(&in[(size_t)idx * D4 + c4]);

    for (;;) {
        const int nidx = idx + NCTA;
        float4 vn;
        const bool more = (nidx < NTASK);
        if (more)
            vn = __ldg(&in[(size_t)nidx * D4 + c4]);   // prefetch next task

        const int b = idx >> 12;          // idx / S   (S = 4096)
        const int s = idx & (S - 1);      // idx % S
        scatter_row(out, b, s, c4, v);

        if (!more) break;
        v = vn;
        idx = nidx;
    }
}

extern "C" void kernel_launch(void* const* d_in, const int* in_sizes, int n_in,
                              void* d_out, int out_size) {
    const float4* in = (const float4*)d_in[0];
    float4* out = (float4*)d_out;

    delay_buffer_persist_kernel<<<NCTA, D4>>>(in, out);
}

// round 13
// speedup vs baseline: 1.1527x; 1.1527x over previous
#include <cuda_runtime.h>

// DelayBuffer: out[b, t, i*D + c] = emb[b, t - d_i, c] if t >= d_i else emb[b, t, c]
// d_i in (1, 2, 4, 8, 16, 32) = 1 << i
// B=4, S=4096, D=1024 (fp32). Output [B, S, 6*D].
//
// Proven-best per-thread pattern (R9): 6 front-batched float4 loads (MLP=6)
// then 6 streaming float4 stores. This round folds TWO consecutive t-rows
// into one 512-thread block (threads 0-255 -> row t0, threads 256-511 ->
// row t0+1): identical memory pattern per thread, half the CTA count
// (16384 -> 8192), fewer block-dispatch transitions. Input (64 MiB) stays
// L2-resident because the 402 MiB output streams out with evict-first stores.

static constexpr int B  = 4;
static constexpr int S  = 4096;
static constexpr int D  = 1024;
static constexpr int D4 = D / 4;     // 256 float4 per segment
static constexpr int ND = 6;         // number of delays
static constexpr int TPB = 2;        // t-rows per block
static constexpr int NT  = TPB * D4; // 512 threads

__global__ __launch_bounds__(NT, 4)
void delay_buffer_kernel(const float4* __restrict__ in, float4* __restrict__ out) {
    const int c4 = threadIdx.x & (D4 - 1);        // 0..255 within a segment
    const int j  = threadIdx.x >> 8;              // which of the 2 rows
    const int t  = blockIdx.x * TPB + j;          // 0..4095
    const int b  = blockIdx.y;                    // 0..3

    // 6 independent loads, front-batched for MLP
    float4 v[ND];
#pragma unroll
    for (int i = 0; i < ND; i++) {
        const int d = 1 << i;                     // DELAYS = (1,2,4,8,16,32)
        const int src_t = (t >= d) ? (t - d) : t;
        v[i] = __ldg(&in[(b * S + src_t) * D4 + c4]);
    }

    // 6 streaming stores into the contiguous output row [row, 6*D]
    float4* orow = out + (size_t)(b * S + t) * (ND * D4) + c4;
#pragma unroll
    for (int i = 0; i < ND; i++) {
        __stcs(orow + i * D4, v[i]);
    }
}

extern "C" void kernel_launch(void* const* d_in, const int* in_sizes, int n_in,
                              void* d_out, int out_size) {
    const float4* in = (const float4*)d_in[0];
    float4* out = (float4*)d_out;

    dim3 grid(S / TPB, B);
    delay_buffer_kernel<<<grid, NT>>>(in, out);
}